// round 12
// baseline (speedup 1.0000x reference)
#include <cuda_runtime.h>
#include <cstdint>

// Problem shape (fixed by the dataset):
//   features:        (BS=4, C=64, P=12000) float32
//   x_orig_indices:  (BS, P) int32  (JAX x64 disabled: "int64" is silently int32)
//   y_orig_indices:  (BS, P) int32
//   output pseudo:   (BS, C, NY=440, NX=500) float32
#define BS     4
#define CCH    64
#define NP     12000
#define NXP    500
#define NYP    440
#define CELLS  (NXP * NYP)          // 220000
#define CELLS8 (CELLS / 8)          // 27500 cell8-groups per batch
#define NWORDS ((CELLS8 + 31) / 32) // 860 bitmap words per batch
#define NPLANES (BS * CCH)          // 256 output planes
#define PL_PER_CHUNK 16             // planes per memset/overwrite chunk (14.08MB)
#define NCHK   (NPLANES / PL_PER_CHUNK)  // 16 chunks

// Scratch (allocation-free device globals).
__device__ int            g_winner[BS * CELLS];   // (p+1) or 0; reset by pack
__device__ unsigned short g_w16[BS * CELLS];      // compressed winner
__device__ unsigned int   g_bitmap[BS * NWORDS];  // 1 bit per cell8 group

// ---------------------------------------------------------------------------
// Phase 1: winner pass — JAX sequential .set semantics == last p wins == max p.
// Also zeroes the bitmap for this launch (ordered before pack by kernel edge).
// ---------------------------------------------------------------------------
__global__ void winner_kernel(const int* __restrict__ xi,
                              const int* __restrict__ yi) {
    int i = blockIdx.x * blockDim.x + threadIdx.x;
    if (i < BS * NWORDS) g_bitmap[i] = 0u;
    if (i >= BS * NP) return;
    int b = i / NP;
    int p = i - b * NP;

    int x = xi[i];
    int y = yi[i];
    // jnp.clip semantics
    x = x < 0 ? 0 : (x >= NXP ? NXP - 1 : x);
    y = y < 0 ? 0 : (y >= NYP ? NYP - 1 : y);
    int cell = y * NXP + x;

    atomicMax(&g_winner[b * CELLS + cell], p + 1);
}

// ---------------------------------------------------------------------------
// Phase 2: pack int32 winner -> u16 + bitmap bit per cell8 group; reset the
// int32 winner for the next launch (sole reader -> replay-safe).
// ---------------------------------------------------------------------------
__global__ void pack_kernel() {
    const int n8 = BS * CELLS8;        // 110000
    int i = blockIdx.x * blockDim.x + threadIdx.x;
    if (i >= n8) return;
    int b     = i / CELLS8;
    int group = i - b * CELLS8;

    int4* wp = reinterpret_cast<int4*>(g_winner + b * CELLS) + group * 2;
    int4 w0 = wp[0];
    int4 w1 = wp[1];
    wp[0] = make_int4(0, 0, 0, 0);     // reset for next replay
    wp[1] = make_int4(0, 0, 0, 0);

    uint4 s;
    s.x = (unsigned int)(w0.x & 0xFFFF) | ((unsigned int)w0.y << 16);
    s.y = (unsigned int)(w0.z & 0xFFFF) | ((unsigned int)w0.w << 16);
    s.z = (unsigned int)(w1.x & 0xFFFF) | ((unsigned int)w1.y << 16);
    s.w = (unsigned int)(w1.z & 0xFFFF) | ((unsigned int)w1.w << 16);
    reinterpret_cast<uint4*>(g_w16 + b * CELLS)[group] = s;

    if (s.x | s.y | s.z | s.w)
        atomicOr(&g_bitmap[b * NWORDS + (group >> 5)], 1u << (group & 31));
}

// ---------------------------------------------------------------------------
// Phase 3: sparse overwrite of ONE 16-plane chunk. Runs right after the CE
// memset of the same chunk, while those lines are still dirty in L2 ->
// stores merge into resident lines: zero extra DRAM traffic, L2-speed.
// Only groups with >=1 winner store (full 16B vectors; zero lanes match the
// memset). ~65% of threads exit after one broadcast bitmap-word load.
// ---------------------------------------------------------------------------
__global__ void overwrite_chunk_kernel(const float* __restrict__ feat,
                                       float* __restrict__ out,
                                       int plane0) {
    const int group = blockIdx.x * blockDim.x + threadIdx.x;  // cell8 in plane
    if (group >= CELLS8) return;
    const int bc = plane0 + blockIdx.y;                       // b*CCH + c
    const int b  = bc >> 6;

    // One word covers 32 groups == exactly one warp -> broadcast load.
    unsigned int word = __ldg(&g_bitmap[b * NWORDS + (group >> 5)]);
    if (!((word >> (group & 31)) & 1u)) return;

    uint4 w = __ldg(reinterpret_cast<const uint4*>(g_w16 + b * CELLS) + group);
    const float* frow = feat + (size_t)bc * NP;   // 48KB row, L2-hot
    int p0 = (int)(w.x & 0xFFFFu), p1 = (int)(w.x >> 16);
    int p2 = (int)(w.y & 0xFFFFu), p3 = (int)(w.y >> 16);
    int p4 = (int)(w.z & 0xFFFFu), p5 = (int)(w.z >> 16);
    int p6 = (int)(w.w & 0xFFFFu), p7 = (int)(w.w >> 16);
    float4 v0, v1;
    v0.x = p0 ? __ldg(frow + p0 - 1) : 0.f;
    v0.y = p1 ? __ldg(frow + p1 - 1) : 0.f;
    v0.z = p2 ? __ldg(frow + p2 - 1) : 0.f;
    v0.w = p3 ? __ldg(frow + p3 - 1) : 0.f;
    v1.x = p4 ? __ldg(frow + p4 - 1) : 0.f;
    v1.y = p5 ? __ldg(frow + p5 - 1) : 0.f;
    v1.z = p6 ? __ldg(frow + p6 - 1) : 0.f;
    v1.w = p7 ? __ldg(frow + p7 - 1) : 0.f;

    float4* o = reinterpret_cast<float4*>(out + (size_t)bc * CELLS) + group * 2;
    o[0] = v0;
    o[1] = v1;
}

// ---------------------------------------------------------------------------
// Graph topology (two streams, chunk-pipelined):
//   s2 (CE):  ms_0 -> ms_1 -> ... -> ms_15        (225MB pure-write, ~35us)
//   stream0:  winner -> pack -> [wait ms_0] ow_0 -> [wait ms_1] ow_1 -> ...
// Each overwrite chunk runs while its 14MB chunk is still L2-resident-dirty
// (chunk << 126MB L2; overwrite trails the CE by ~1 chunk).
// Streams/events are host-side objects created once; capture-legal (R10 ran).
// ---------------------------------------------------------------------------
extern "C" void kernel_launch(void* const* d_in, const int* in_sizes, int n_in,
                              void* d_out, int out_size) {
    const float* feat = (const float*)d_in[0];
    const int*   xi   = (const int*)d_in[1];
    const int*   yi   = (const int*)d_in[2];
    float* out = (float*)d_out;

    static cudaStream_t s2 = nullptr;
    static cudaEvent_t  evFork = nullptr;
    static cudaEvent_t  evMs[NCHK];
    if (s2 == nullptr) {
        cudaStreamCreateWithFlags(&s2, cudaStreamNonBlocking);
        cudaEventCreateWithFlags(&evFork, cudaEventDisableTiming);
        for (int k = 0; k < NCHK; k++)
            cudaEventCreateWithFlags(&evMs[k], cudaEventDisableTiming);
    }

    const size_t chunk_elems = (size_t)PL_PER_CHUNK * CELLS;   // 3,520,000

    // Fork the CE stream into the capture; start the memset chain at once.
    cudaEventRecord(evFork, 0);
    cudaStreamWaitEvent(s2, evFork, 0);
    for (int k = 0; k < NCHK; k++) {
        cudaMemsetAsync(out + k * chunk_elems, 0,
                        chunk_elems * sizeof(float), s2);
        cudaEventRecord(evMs[k], s2);
    }

    {   // winner pass (+ bitmap zeroing) — concurrent with early memsets
        int n = BS * NP;
        int threads = 256;
        int blocks = (n + threads - 1) / threads;
        winner_kernel<<<blocks, threads>>>(xi, yi);
    }
    {   // pack to u16 + bitmap + reset
        int n = BS * CELLS8;
        int threads = 256;
        int blocks = (n + threads - 1) / threads;
        pack_kernel<<<blocks, threads>>>();
    }

    // Chunk-pipelined sparse overwrites, each gated on its memset.
    for (int k = 0; k < NCHK; k++) {
        cudaStreamWaitEvent(0, evMs[k], 0);
        dim3 grid((CELLS8 + 255) / 256, PL_PER_CHUNK);   // (108, 16)
        overwrite_chunk_kernel<<<grid, 256>>>(feat, out, k * PL_PER_CHUNK);
    }
}

// round 13
// speedup vs baseline: 1.9972x; 1.9972x over previous
#include <cuda_runtime.h>
#include <cstdint>

// Problem shape (fixed by the dataset):
//   features:        (BS=4, C=64, P=12000) float32
//   x_orig_indices:  (BS, P) int32  (JAX x64 disabled: "int64" is silently int32)
//   y_orig_indices:  (BS, P) int32
//   output pseudo:   (BS, C, NY=440, NX=500) float32
#define BS     4
#define CCH    64
#define NP     12000
#define NXP    500
#define NYP    440
#define CELLS  (NXP * NYP)          // 220000
#define CELLS8 (CELLS / 8)          // 27500 cell8-groups per batch
#define NWORDS ((CELLS8 + 31) / 32) // 860 bitmap words per batch
#define NOUT   (BS * CCH * CELLS)   // 56,320,000
#define N8     (NOUT / 8)           // 7,040,000 cell8-groups total

#define GBLOCKS 608                 // 152 SMs * 4 resident blocks
#define GTHREADS 512

// Scratch (allocation-free device globals).
__device__ int            g_winner[BS * CELLS];   // (p+1) or 0; reset by pack
__device__ unsigned short g_w16[BS * CELLS];      // compressed winner
__device__ unsigned int   g_bitmap[BS * NWORDS];  // 1 bit per cell8 group

// ---------------------------------------------------------------------------
// Phase 1: winner pass — JAX sequential .set semantics == last p wins == max p.
// Vectorized: 4 points per thread (int4 loads). Also zeroes the bitmap.
// ---------------------------------------------------------------------------
__global__ void winner_kernel(const int* __restrict__ xi,
                              const int* __restrict__ yi) {
    int t = blockIdx.x * blockDim.x + threadIdx.x;
    if (t < BS * NWORDS) g_bitmap[t] = 0u;

    const int nq = (BS * NP) / 4;        // 12000 quads
    if (t >= nq) return;
    int i0 = t * 4;                      // global point index of lane 0
    int b  = i0 / NP;                    // NP divisible by 4 -> quad in one batch
    int p0 = i0 - b * NP;

    int4 x4 = reinterpret_cast<const int4*>(xi)[t];
    int4 y4 = reinterpret_cast<const int4*>(yi)[t];

    int xs[4] = {x4.x, x4.y, x4.z, x4.w};
    int ys[4] = {y4.x, y4.y, y4.z, y4.w};
    #pragma unroll
    for (int j = 0; j < 4; j++) {
        int x = xs[j], y = ys[j];
        x = x < 0 ? 0 : (x >= NXP ? NXP - 1 : x);   // jnp.clip
        y = y < 0 ? 0 : (y >= NYP ? NYP - 1 : y);
        atomicMax(&g_winner[b * CELLS + y * NXP + x], p0 + j + 1);
    }
}

// ---------------------------------------------------------------------------
// Phase 2: pack int32 winner -> u16 + bitmap bit per cell8 group; reset the
// int32 winner for the next launch (sole reader -> replay-safe).
// ---------------------------------------------------------------------------
__global__ void pack_kernel() {
    const int n8 = BS * CELLS8;        // 110000
    int i = blockIdx.x * blockDim.x + threadIdx.x;
    if (i >= n8) return;
    int b     = i / CELLS8;
    int group = i - b * CELLS8;

    int4* wp = reinterpret_cast<int4*>(g_winner + b * CELLS) + group * 2;
    int4 w0 = wp[0];
    int4 w1 = wp[1];
    wp[0] = make_int4(0, 0, 0, 0);     // reset for next replay
    wp[1] = make_int4(0, 0, 0, 0);

    uint4 s;
    s.x = (unsigned int)(w0.x & 0xFFFF) | ((unsigned int)w0.y << 16);
    s.y = (unsigned int)(w0.z & 0xFFFF) | ((unsigned int)w0.w << 16);
    s.z = (unsigned int)(w1.x & 0xFFFF) | ((unsigned int)w1.y << 16);
    s.w = (unsigned int)(w1.z & 0xFFFF) | ((unsigned int)w1.w << 16);
    reinterpret_cast<uint4*>(g_w16 + b * CELLS)[group] = s;

    if (s.x | s.y | s.z | s.w)
        atomicOr(&g_bitmap[b * NWORDS + (group >> 5)], 1u << (group & 31));
}

// ---------------------------------------------------------------------------
// Phase 3: PERSISTENT fused zero-fill + gather. 608 resident blocks grid-
// stride over all 7.04M cell8 groups: warps live for the whole kernel and
// emit back-to-back streaming stores (memset-like), no CTA churn, and the
// instantaneous store window is one contiguous ~10MB span sweeping linearly.
// Fast path (~65%): L1-resident bitmap word -> two dependency-free zero
// stores. Slow path: w16 + up to 8 L2-hot feature gathers.
// ---------------------------------------------------------------------------
__device__ __forceinline__ void do_group(const float* __restrict__ feat,
                                         float4* __restrict__ out4,
                                         int idx) {
    int bc    = idx / CELLS8;                       // plane
    int group = idx - bc * CELLS8;
    int b     = bc >> 6;

    unsigned int word = __ldg(&g_bitmap[b * NWORDS + (group >> 5)]);
    float4* o = out4 + (size_t)idx * 2;

    if (!((word >> (group & 31)) & 1u)) {
        const float4 z = make_float4(0.f, 0.f, 0.f, 0.f);
        __stcs(o,     z);
        __stcs(o + 1, z);
    } else {
        uint4 w = __ldg(reinterpret_cast<const uint4*>(g_w16 + b * CELLS) + group);
        const float* frow = feat + (size_t)bc * NP;
        int p0 = (int)(w.x & 0xFFFFu), p1 = (int)(w.x >> 16);
        int p2 = (int)(w.y & 0xFFFFu), p3 = (int)(w.y >> 16);
        int p4 = (int)(w.z & 0xFFFFu), p5 = (int)(w.z >> 16);
        int p6 = (int)(w.w & 0xFFFFu), p7 = (int)(w.w >> 16);
        float4 v0, v1;
        v0.x = p0 ? __ldg(frow + p0 - 1) : 0.f;
        v0.y = p1 ? __ldg(frow + p1 - 1) : 0.f;
        v0.z = p2 ? __ldg(frow + p2 - 1) : 0.f;
        v0.w = p3 ? __ldg(frow + p3 - 1) : 0.f;
        v1.x = p4 ? __ldg(frow + p4 - 1) : 0.f;
        v1.y = p5 ? __ldg(frow + p5 - 1) : 0.f;
        v1.z = p6 ? __ldg(frow + p6 - 1) : 0.f;
        v1.w = p7 ? __ldg(frow + p7 - 1) : 0.f;
        __stcs(o,     v0);
        __stcs(o + 1, v1);
    }
}

__global__ void __launch_bounds__(GTHREADS)
gather_kernel(const float* __restrict__ feat,
              float* __restrict__ out) {
    const int stride = GBLOCKS * GTHREADS;          // 311,296
    float4* out4 = reinterpret_cast<float4*>(out);

    int idx = blockIdx.x * GTHREADS + threadIdx.x;
    // Unroll-by-2 grid-stride: two independent groups in flight per iter.
    for (; idx + stride < N8; idx += 2 * stride) {
        do_group(feat, out4, idx);
        do_group(feat, out4, idx + stride);
    }
    if (idx < N8) do_group(feat, out4, idx);
}

// ---------------------------------------------------------------------------
extern "C" void kernel_launch(void* const* d_in, const int* in_sizes, int n_in,
                              void* d_out, int out_size) {
    const float* feat = (const float*)d_in[0];
    const int*   xi   = (const int*)d_in[1];
    const int*   yi   = (const int*)d_in[2];
    float* out = (float*)d_out;

    {   // winner pass (4 points/thread, + bitmap zeroing)
        int n = BS * NWORDS > (BS * NP) / 4 ? BS * NWORDS : (BS * NP) / 4;
        int threads = 256;
        int blocks = (n + threads - 1) / threads;
        winner_kernel<<<blocks, threads>>>(xi, yi);
    }
    {   // pack to u16 + bitmap + reset
        int n = BS * CELLS8;
        int threads = 256;
        int blocks = (n + threads - 1) / threads;
        pack_kernel<<<blocks, threads>>>();
    }
    {   // persistent fused zero + gather
        gather_kernel<<<GBLOCKS, GTHREADS>>>(feat, out);
    }
}

// round 14
// speedup vs baseline: 2.2520x; 1.1276x over previous
#include <cuda_runtime.h>
#include <cstdint>

// Problem shape (fixed by the dataset):
//   features:        (BS=4, C=64, P=12000) float32
//   x_orig_indices:  (BS, P) int32  (JAX x64 disabled: "int64" is silently int32)
//   y_orig_indices:  (BS, P) int32
//   output pseudo:   (BS, C, NY=440, NX=500) float32
#define BS     4
#define CCH    64
#define NP     12000
#define NXP    500
#define NYP    440
#define CELLS  (NXP * NYP)          // 220000
#define CELLS8 (CELLS / 8)          // 27500 cell8-groups per batch
#define NWORDS ((CELLS8 + 31) / 32) // 860 bitmap words per batch

#define TCHUNK  4096                // cells per tile (16KB fp32)
#define NTILE   ((CELLS + TCHUNK - 1) / TCHUNK)  // 54 (last tile = 2848 cells)

// Scratch (allocation-free device globals).
__device__ int            g_winner[BS * CELLS];   // (p+1) or 0; reset by pack
__device__ unsigned short g_w16[BS * CELLS];      // compressed winner
__device__ unsigned int   g_bitmap[BS * NWORDS];  // 1 bit per cell8 group

// ---------------------------------------------------------------------------
// Phase 1: winner pass — JAX sequential .set semantics == last p wins == max p.
// Also zeroes the bitmap (ordered before pack's atomicOr by kernel boundary).
// ---------------------------------------------------------------------------
__global__ void winner_kernel(const int* __restrict__ xi,
                              const int* __restrict__ yi) {
    int i = blockIdx.x * blockDim.x + threadIdx.x;
    if (i < BS * NWORDS) g_bitmap[i] = 0u;
    if (i >= BS * NP) return;
    int b = i / NP;
    int p = i - b * NP;

    int x = xi[i];
    int y = yi[i];
    // jnp.clip semantics
    x = x < 0 ? 0 : (x >= NXP ? NXP - 1 : x);
    y = y < 0 ? 0 : (y >= NYP ? NYP - 1 : y);
    int cell = y * NXP + x;

    atomicMax(&g_winner[b * CELLS + cell], p + 1);
}

// ---------------------------------------------------------------------------
// Phase 2: pack int32 winner -> u16 + bitmap bit per cell8 group; reset the
// int32 winner for the next launch (sole reader -> replay-safe).
// ---------------------------------------------------------------------------
__global__ void pack_kernel() {
    const int n8 = BS * CELLS8;        // 110000
    int i = blockIdx.x * blockDim.x + threadIdx.x;
    if (i >= n8) return;
    int b     = i / CELLS8;
    int group = i - b * CELLS8;

    int4* wp = reinterpret_cast<int4*>(g_winner + b * CELLS) + group * 2;
    int4 w0 = wp[0];
    int4 w1 = wp[1];
    wp[0] = make_int4(0, 0, 0, 0);     // reset for next replay
    wp[1] = make_int4(0, 0, 0, 0);

    uint4 s;
    s.x = (unsigned int)(w0.x & 0xFFFF) | ((unsigned int)w0.y << 16);
    s.y = (unsigned int)(w0.z & 0xFFFF) | ((unsigned int)w0.w << 16);
    s.z = (unsigned int)(w1.x & 0xFFFF) | ((unsigned int)w1.y << 16);
    s.w = (unsigned int)(w1.z & 0xFFFF) | ((unsigned int)w1.w << 16);
    reinterpret_cast<uint4*>(g_w16 + b * CELLS)[group] = s;

    if (s.x | s.y | s.z | s.w)
        atomicOr(&g_bitmap[b * NWORDS + (group >> 5)], 1u << (group & 31));
}

// ---------------------------------------------------------------------------
// Phase 3: TMA-store gather, ONE TILE PER BLOCK (no channel serialization —
// this is the fix for R8). The fused-STG gather is pinned at ~56us by the
// L1TEX store-wavefront rate (1x128B/cyc/SM); cp.async.bulk SMEM->global goes
// down the async proxy, bypassing L1TEX, and hits the LTS/DRAM at
// memset-class efficiency.
//   block = 16KB tile of one plane: zero smem, overwrite winner cells
//   (bitmap fast-skip, w16 + L2-hot feat gathers), one bulk store, drain.
// Grid (54, 256): consecutive blocks sweep each plane linearly (proven best
// DRAM order). ~8 resident blocks/SM overlap fill and drain phases.
// ---------------------------------------------------------------------------
__global__ void __launch_bounds__(256)
tma_gather_kernel(const float* __restrict__ feat,
                  float* __restrict__ out) {
    __shared__ __align__(16) float tile[TCHUNK];   // 16KB

    const int chunk = blockIdx.x;                  // tile within plane
    const int bc    = blockIdx.y;                  // plane = b*CCH + c
    const int b     = bc >> 6;
    const int cell0 = chunk * TCHUNK;
    const int ncell = min(TCHUNK, CELLS - cell0);  // 4096 or 2848 (mult of 8)

    // Zero the smem tile (128B/cyc/SM smem BW -> trivial).
    {
        float4* t4 = reinterpret_cast<float4*>(tile);
        const float4 z = make_float4(0.f, 0.f, 0.f, 0.f);
        #pragma unroll
        for (int k = 0; k < TCHUNK / 4 / 256; k++)  // 4 iters
            t4[threadIdx.x + k * 256] = z;
    }
    __syncthreads();

    // Overwrite winner cells. One thread per cell8 group (512 groups/tile).
    {
        const int g0 = cell0 >> 3;
        const int ng = ncell >> 3;                 // 512 or 356
        const float* frow = feat + (size_t)bc * NP;
        for (int g = threadIdx.x; g < ng; g += 256) {
            const int group = g0 + g;
            unsigned int word = __ldg(&g_bitmap[b * NWORDS + (group >> 5)]);
            if (!((word >> (group & 31)) & 1u)) continue;

            uint4 w = __ldg(reinterpret_cast<const uint4*>(g_w16 + b * CELLS) + group);
            int p0 = (int)(w.x & 0xFFFFu), p1 = (int)(w.x >> 16);
            int p2 = (int)(w.y & 0xFFFFu), p3 = (int)(w.y >> 16);
            int p4 = (int)(w.z & 0xFFFFu), p5 = (int)(w.z >> 16);
            int p6 = (int)(w.w & 0xFFFFu), p7 = (int)(w.w >> 16);
            float4 v0, v1;
            v0.x = p0 ? __ldg(frow + p0 - 1) : 0.f;
            v0.y = p1 ? __ldg(frow + p1 - 1) : 0.f;
            v0.z = p2 ? __ldg(frow + p2 - 1) : 0.f;
            v0.w = p3 ? __ldg(frow + p3 - 1) : 0.f;
            v1.x = p4 ? __ldg(frow + p4 - 1) : 0.f;
            v1.y = p5 ? __ldg(frow + p5 - 1) : 0.f;
            v1.z = p6 ? __ldg(frow + p6 - 1) : 0.f;
            v1.w = p7 ? __ldg(frow + p7 - 1) : 0.f;
            float4* dst = reinterpret_cast<float4*>(tile + g * 8);
            dst[0] = v0;
            dst[1] = v1;
        }
    }
    __syncthreads();

    // One bulk async store: 16KB (or 11392B tail) SMEM -> global, async proxy.
    if (threadIdx.x == 0) {
        uint32_t saddr;
        asm("{ .reg .u64 t; cvta.to.shared.u64 t, %1; cvt.u32.u64 %0, t; }"
            : "=r"(saddr) : "l"(tile));
        asm volatile("fence.proxy.async.shared::cta;" ::: "memory");
        asm volatile(
            "cp.async.bulk.global.shared::cta.bulk_group [%0], [%1], %2;"
            :: "l"(out + (size_t)bc * CELLS + cell0), "r"(saddr),
               "r"(ncell * 4)
            : "memory");
        asm volatile("cp.async.bulk.commit_group;" ::: "memory");
        // Must drain before the CTA (and its smem) retires.
        asm volatile("cp.async.bulk.wait_group 0;" ::: "memory");
    }
    __syncthreads();
}

// ---------------------------------------------------------------------------
extern "C" void kernel_launch(void* const* d_in, const int* in_sizes, int n_in,
                              void* d_out, int out_size) {
    const float* feat = (const float*)d_in[0];
    const int*   xi   = (const int*)d_in[1];
    const int*   yi   = (const int*)d_in[2];
    float* out = (float*)d_out;

    {   // winner pass (+ bitmap zeroing)
        int n = BS * NP;
        int threads = 256;
        int blocks = (n + threads - 1) / threads;
        winner_kernel<<<blocks, threads>>>(xi, yi);
    }
    {   // pack to u16 + bitmap + reset
        int n = BS * CELLS8;
        int threads = 256;
        int blocks = (n + threads - 1) / threads;
        pack_kernel<<<blocks, threads>>>();
    }
    {   // TMA-store gather: one 16KB tile per block, no serialization
        dim3 grid(NTILE, BS * CCH);   // (54, 256) = 13824 blocks
        tma_gather_kernel<<<grid, 256>>>(feat, out);
    }
}